// round 3
// baseline (speedup 1.0000x reference)
#include <cuda_runtime.h>
#include <math.h>

#define D_MODEL 256
#define NHEAD 8
#define DHEAD 32
#define D_FF 1024
#define N_BLOCKS 2
#define BATCH 256
#define INTER 50
#define INTRA 20
#define CAND 2048
#define NTOK (BATCH*INTER)
#define NEG_INF -1.0e9f

// ---------------- scratch (device globals; allocation-free) ----------------
__device__ __align__(256) float g_Ehat[NTOK*D_MODEL];
__device__ __align__(256) float g_S [NTOK*D_MODEL];
__device__ __align__(256) float g_Yb [NTOK*D_MODEL];
__device__ __align__(256) float g_Qb [NTOK*D_MODEL];
__device__ __align__(256) float g_Kb [NTOK*D_MODEL];
__device__ __align__(256) float g_Vb [NTOK*D_MODEL];
__device__ __align__(256) float g_Tb [NTOK*D_MODEL];
__device__ __align__(256) float g_Hb [NTOK*D_FF];
__device__ __align__(256) float g_ushort[BATCH*D_MODEL];
__device__ __align__(256) float g_ulong [BATCH*D_MODEL];
__device__ __align__(256) float g_Ugate [BATCH*D_MODEL];

// ---------------- intra-session attention -> E_hat ----------------
// One block per session (12800). E_hat = sum_k (sum_q p[q,k]) * x[k].
__global__ __launch_bounds__(128) void intra_kernel(const float* __restrict__ item_emb,
                                                    const int* __restrict__ sessions) {
    __shared__ float x[INTRA][260];            // padded rows, 16B-aligned stride
    __shared__ float sc[INTRA][INTRA+1];
    __shared__ float wsum[INTRA];
    __shared__ int   idxs[INTRA];
    const int n = blockIdx.x;
    const int t = threadIdx.x;

    if (t < INTRA) idxs[t] = sessions[n*INTRA + t];
    __syncthreads();

    // load x (20 x 256), zero row for pad index 0
    for (int j = t; j < INTRA*64; j += 128) {
        int r = j >> 6, c = j & 63;
        float4 v = make_float4(0.f,0.f,0.f,0.f);
        int idx = idxs[r];
        if (idx != 0) v = *(const float4*)(item_emb + (size_t)idx*D_MODEL + c*4);
        *(float4*)&x[r][c*4] = v;
    }
    __syncthreads();

    // scores: thread (qp, c) handles q rows {2qp,2qp+1}, 32-float chunk c
    if (t < 80) {
        const int qp = t >> 3, c = t & 7;
        const unsigned mask = (t >= 64) ? 0x0000ffffu : 0xffffffffu;
        float4 qA[8], qB[8];
        #pragma unroll
        for (int i = 0; i < 8; i++) {
            qA[i] = *(const float4*)&x[2*qp  ][c*32 + i*4];
            qB[i] = *(const float4*)&x[2*qp+1][c*32 + i*4];
        }
        for (int k = 0; k < INTRA; k++) {
            float sa = 0.f, sb = 0.f;
            #pragma unroll
            for (int i = 0; i < 8; i++) {
                float4 bv = *(const float4*)&x[k][c*32 + i*4];
                sa += qA[i].x*bv.x + qA[i].y*bv.y + qA[i].z*bv.z + qA[i].w*bv.w;
                sb += qB[i].x*bv.x + qB[i].y*bv.y + qB[i].z*bv.z + qB[i].w*bv.w;
            }
            sa += __shfl_xor_sync(mask, sa, 1);
            sa += __shfl_xor_sync(mask, sa, 2);
            sa += __shfl_xor_sync(mask, sa, 4);
            sb += __shfl_xor_sync(mask, sb, 1);
            sb += __shfl_xor_sync(mask, sb, 2);
            sb += __shfl_xor_sync(mask, sb, 4);
            if (c == 0) {
                sc[2*qp  ][k] = sa * 0.0625f;   // 1/sqrt(256)
                sc[2*qp+1][k] = sb * 0.0625f;
            }
        }
    }
    __syncthreads();

    // masked softmax per q row
    if (t < INTRA) {
        float v[INTRA];
        float mx = -3.0e38f;
        #pragma unroll
        for (int k = 0; k < INTRA; k++) {
            float s = (idxs[k] != 0) ? sc[t][k] : NEG_INF;
            v[k] = s; mx = fmaxf(mx, s);
        }
        float sum = 0.f;
        #pragma unroll
        for (int k = 0; k < INTRA; k++) { float e = __expf(v[k]-mx); v[k] = e; sum += e; }
        float inv = 1.f/sum;
        #pragma unroll
        for (int k = 0; k < INTRA; k++) sc[t][k] = v[k]*inv;
    }
    __syncthreads();

    if (t < INTRA) {           // column sums
        float w = 0.f;
        #pragma unroll
        for (int q = 0; q < INTRA; q++) w += sc[q][t];
        wsum[t] = w;
    }
    __syncthreads();

    float* outp = g_Ehat + (size_t)n*D_MODEL;
    for (int d = t; d < D_MODEL; d += 128) {
        float acc = 0.f;
        #pragma unroll
        for (int k = 0; k < INTRA; k++) acc += wsum[k]*x[k][d];
        outp[d] = acc;
    }
}

// ---------------- S = E_hat + PE ; u_short = E_hat[:, -1, :] ----------------
__global__ __launch_bounds__(256) void initS_kernel() {
    int i = blockIdx.x*256 + threadIdx.x;
    int d = i & 255;
    int tok = i >> 8;
    int pos = tok % INTER;
    int j = d >> 1;
    float div = expf((float)(2*j) * (-0.03597789207803197f));   // -ln(1e4)/256
    float ang = (float)pos * div;
    float pe = (d & 1) ? cosf(ang) : sinf(ang);
    float eh = g_Ehat[i];
    g_S[i] = eh + pe;
    if (pos == INTER-1) g_ushort[(tok/INTER)*D_MODEL + d] = eh;
}

// ---------------- LayerNorm (ddof=1, eps added to std) ----------------
__global__ __launch_bounds__(256) void ln_kernel(const float* __restrict__ x, float* __restrict__ y,
                                                 const float* __restrict__ g, const float* __restrict__ b) {
    const int tok  = blockIdx.x*8 + (threadIdx.x >> 5);
    const int lane = threadIdx.x & 31;
    const float4* xr = (const float4*)(x + (size_t)tok*D_MODEL);
    float4 a = xr[lane*2], c = xr[lane*2+1];
    float s  = a.x+a.y+a.z+a.w + c.x+c.y+c.z+c.w;
    float ss = a.x*a.x+a.y*a.y+a.z*a.z+a.w*a.w + c.x*c.x+c.y*c.y+c.z*c.z+c.w*c.w;
    #pragma unroll
    for (int o = 16; o > 0; o >>= 1) {
        s  += __shfl_xor_sync(0xffffffffu, s , o);
        ss += __shfl_xor_sync(0xffffffffu, ss, o);
    }
    float m   = s * (1.f/256.f);
    float var = fmaxf((ss - 256.f*m*m) * (1.f/255.f), 0.f);
    float inv = 1.f/(sqrtf(var) + 1e-6f);
    float4 g0 = ((const float4*)g)[lane*2], g1 = ((const float4*)g)[lane*2+1];
    float4 b0 = ((const float4*)b)[lane*2], b1 = ((const float4*)b)[lane*2+1];
    float4 o0, o1;
    o0.x = g0.x*(a.x-m)*inv + b0.x;  o0.y = g0.y*(a.y-m)*inv + b0.y;
    o0.z = g0.z*(a.z-m)*inv + b0.z;  o0.w = g0.w*(a.w-m)*inv + b0.w;
    o1.x = g1.x*(c.x-m)*inv + b1.x;  o1.y = g1.y*(c.y-m)*inv + b1.y;
    o1.z = g1.z*(c.z-m)*inv + b1.z;  o1.w = g1.w*(c.w-m)*inv + b1.w;
    float4* yr = (float4*)(y + (size_t)tok*D_MODEL);
    yr[lane*2] = o0; yr[lane*2+1] = o1;
}

// ---------------- SGEMM: C = A@W + bias (+relu | +res) ----------------
// BM=128 BN=64 BK=16, 256 threads, 8x4 per thread. M%128==0, N%64==0, K%16==0.
template<int MODE>   // 0: bias, 1: bias+relu, 2: bias+residual
__global__ __launch_bounds__(256) void sgemm_kernel(
    const float* __restrict__ A, const float* __restrict__ W,
    const float* __restrict__ bias, const float* __restrict__ res,
    float* __restrict__ C, int M, int N, int K) {
    __shared__ float As[16][132];
    __shared__ float Bs[16][68];
    const int t  = threadIdx.x;
    const int bm = blockIdx.y * 128;
    const int bn = blockIdx.x * 64;
    const int tx = t & 15;
    const int ty = t >> 4;
    const int br = t >> 4, bc = t & 15;
    float acc[8][4];
    #pragma unroll
    for (int i = 0; i < 8; i++)
        #pragma unroll
        for (int j = 0; j < 4; j++) acc[i][j] = 0.f;

    for (int k0 = 0; k0 < K; k0 += 16) {
        #pragma unroll
        for (int i = 0; i < 2; i++) {
            int j = t + i*256;
            int r = j >> 2, c = j & 3;
            float4 v = *(const float4*)(A + (size_t)(bm + r)*K + k0 + c*4);
            As[c*4+0][r] = v.x; As[c*4+1][r] = v.y; As[c*4+2][r] = v.z; As[c*4+3][r] = v.w;
        }
        float4 w4 = *(const float4*)(W + (size_t)(k0 + br)*N + bn + bc*4);
        *(float4*)&Bs[br][bc*4] = w4;
        __syncthreads();
        #pragma unroll
        for (int kk = 0; kk < 16; kk++) {
            float4 a0 = *(const float4*)&As[kk][ty*8];
            float4 a1 = *(const float4*)&As[kk][ty*8+4];
            float4 b4 = *(const float4*)&Bs[kk][tx*4];
            float am[8] = {a0.x,a0.y,a0.z,a0.w,a1.x,a1.y,a1.z,a1.w};
            float bv[4] = {b4.x,b4.y,b4.z,b4.w};
            #pragma unroll
            for (int i = 0; i < 8; i++)
                #pragma unroll
                for (int j = 0; j < 4; j++) acc[i][j] += am[i]*bv[j];
        }
        __syncthreads();
    }
    float4 bb = *(const float4*)(bias + bn + tx*4);
    #pragma unroll
    for (int i = 0; i < 8; i++) {
        size_t off = (size_t)(bm + ty*8 + i)*N + bn + tx*4;
        float4 o;
        o.x = acc[i][0] + bb.x; o.y = acc[i][1] + bb.y;
        o.z = acc[i][2] + bb.z; o.w = acc[i][3] + bb.w;
        if (MODE == 1) {
            o.x = fmaxf(o.x,0.f); o.y = fmaxf(o.y,0.f);
            o.z = fmaxf(o.z,0.f); o.w = fmaxf(o.w,0.f);
        }
        if (MODE == 2) {
            float4 r4 = *(const float4*)(res + off);
            o.x += r4.x; o.y += r4.y; o.z += r4.z; o.w += r4.w;
        }
        *(float4*)(C + off) = o;
    }
}

// ---------------- inter attention: per (batch, head) ----------------
__global__ __launch_bounds__(128) void attn_kernel(const int* __restrict__ sessions) {
    const int b = blockIdx.x, h = blockIdx.y;
    __shared__ float ks[INTER][36];
    __shared__ float vs[INTER][36];
    __shared__ float sc[INTER][53];
    __shared__ int   valid[INTER];
    const int t = threadIdx.x;

    if (t < INTER) valid[t] = sessions[(size_t)(b*INTER + t)*INTRA];
    const float* Kb = g_Kb + (size_t)b*INTER*D_MODEL + h*DHEAD;
    const float* Vb = g_Vb + (size_t)b*INTER*D_MODEL + h*DHEAD;
    for (int j = t; j < INTER*8; j += 128) {
        int r = j >> 3, c = j & 7;
        *(float4*)&ks[r][c*4] = *(const float4*)(Kb + (size_t)r*D_MODEL + c*4);
        *(float4*)&vs[r][c*4] = *(const float4*)(Vb + (size_t)r*D_MODEL + c*4);
    }
    __syncthreads();

    if (t < INTER) {
        const float* Qr = g_Qb + (size_t)(b*INTER + t)*D_MODEL + h*DHEAD;
        float4 q[8];
        #pragma unroll
        for (int i = 0; i < 8; i++) q[i] = *(const float4*)(Qr + i*4);
        float mx = -3.0e38f;
        for (int k = 0; k < INTER; k++) {
            float s = 0.f;
            #pragma unroll
            for (int i = 0; i < 8; i++) {
                float4 kv = *(const float4*)&ks[k][i*4];
                s += q[i].x*kv.x + q[i].y*kv.y + q[i].z*kv.z + q[i].w*kv.w;
            }
            s = (valid[k] != 0) ? s*0.17677669529663688f : NEG_INF;  // 1/sqrt(32)
            sc[t][k] = s; mx = fmaxf(mx, s);
        }
        float sum = 0.f;
        for (int k = 0; k < INTER; k++) { float e = __expf(sc[t][k]-mx); sc[t][k] = e; sum += e; }
        float inv = 1.f/sum;
        for (int k = 0; k < INTER; k++) sc[t][k] *= inv;
    }
    __syncthreads();

    float* Ob = g_Tb + (size_t)b*INTER*D_MODEL + h*DHEAD;
    for (int e = t; e < INTER*DHEAD; e += 128) {
        int q = e >> 5, d = e & 31;
        float acc = 0.f;
        #pragma unroll 10
        for (int k = 0; k < INTER; k++) acc += sc[q][k]*vs[k][d];
        Ob[(size_t)q*D_MODEL + d] = acc;
    }
}

// ---------------- u_long = sum_tokens(LN(S)) + user_emb ----------------
__global__ __launch_bounds__(256) void ulong_kernel(const float* __restrict__ user_emb,
                                                    const int* __restrict__ us) {
    const int b = blockIdx.x, d = threadIdx.x;
    float acc = 0.f;
    const float* Yb = g_Yb + (size_t)b*INTER*D_MODEL + d;
    #pragma unroll 10
    for (int i = 0; i < INTER; i++) acc += Yb[(size_t)i*D_MODEL];
    g_ulong[b*D_MODEL + d] = acc + user_emb[(size_t)us[b]*D_MODEL + d];
}

// ---------------- gate + fuse: 8 batch rows per block ----------------
__global__ __launch_bounds__(256) void gate_kernel(
    const float* __restrict__ Wl, const float* __restrict__ Ws,
    const float* __restrict__ Wt, const float* __restrict__ gb,
    const float* __restrict__ time_emb, const int* __restrict__ tdl) {
    __shared__ float ul[8][260], uss[8][260], te[8][260];
    const int t = threadIdx.x;
    const int b0 = blockIdx.x*8;
    for (int j = t; j < 8*64; j += 256) {
        int bi = j >> 6, c = j & 63;
        *(float4*)&ul [bi][c*4] = *(const float4*)(g_ulong  + (size_t)(b0+bi)*D_MODEL + c*4);
        *(float4*)&uss[bi][c*4] = *(const float4*)(g_ushort + (size_t)(b0+bi)*D_MODEL + c*4);
        *(float4*)&te [bi][c*4] = *(const float4*)(time_emb + (size_t)tdl[b0+bi]*D_MODEL + c*4);
    }
    __syncthreads();
    const int d = t;
    float acc[8] = {0.f,0.f,0.f,0.f,0.f,0.f,0.f,0.f};
    for (int k = 0; k < D_MODEL; k++) {
        float wl = Wl[(size_t)k*D_MODEL + d];
        float ws = Ws[(size_t)k*D_MODEL + d];
        float wt = Wt[(size_t)k*D_MODEL + d];
        #pragma unroll
        for (int bi = 0; bi < 8; bi++)
            acc[bi] += ul[bi][k]*wl + uss[bi][k]*ws + te[bi][k]*wt;
    }
    float gbv = gb[d];
    #pragma unroll
    for (int bi = 0; bi < 8; bi++) {
        float z  = acc[bi] + gbv;
        float tg = 1.f/(1.f + expf(-z));
        g_Ugate[(size_t)(b0+bi)*D_MODEL + d] = tg*uss[bi][d] + (1.f-tg)*ul[bi][d];
    }
}

// ---------------- candidate scoring ----------------
__global__ __launch_bounds__(256) void score_kernel(const float* __restrict__ item_emb,
                                                    const int* __restrict__ pred,
                                                    float* __restrict__ out) {
    const int b = blockIdx.x;
    const int warp = threadIdx.x >> 5, lane = threadIdx.x & 31;
    const int wg = blockIdx.y*8 + warp;              // 0..31
    const float4* up = (const float4*)(g_Ugate + (size_t)b*D_MODEL);
    float4 ua = up[lane*2], ub = up[lane*2+1];
    const int cbase = b*CAND;
    for (int c0 = wg*64; c0 < wg*64 + 64; c0 += 2) {
        int i0 = pred[cbase + c0];
        int i1 = pred[cbase + c0 + 1];
        const float4* r0 = (const float4*)(item_emb + (size_t)i0*D_MODEL);
        const float4* r1 = (const float4*)(item_emb + (size_t)i1*D_MODEL);
        float4 a0 = r0[lane*2], b0 = r0[lane*2+1];
        float4 a1 = r1[lane*2], b1 = r1[lane*2+1];
        float s0 = a0.x*ua.x + a0.y*ua.y + a0.z*ua.z + a0.w*ua.w
                 + b0.x*ub.x + b0.y*ub.y + b0.z*ub.z + b0.w*ub.w;
        float s1 = a1.x*ua.x + a1.y*ua.y + a1.z*ua.z + a1.w*ua.w
                 + b1.x*ub.x + b1.y*ub.y + b1.z*ub.z + b1.w*ub.w;
        #pragma unroll
        for (int o = 16; o > 0; o >>= 1) {
            s0 += __shfl_xor_sync(0xffffffffu, s0, o);
            s1 += __shfl_xor_sync(0xffffffffu, s1, o);
        }
        if (lane == 0) {
            out[(size_t)cbase + c0]     = s0;
            out[(size_t)cbase + c0 + 1] = s1;
        }
    }
}

// ---------------- launcher ----------------
extern "C" void kernel_launch(void* const* d_in, const int* in_sizes, int n_in,
                              void* d_out, int out_size) {
    (void)in_sizes; (void)n_in; (void)out_size;
    const float* item_emb = (const float*)d_in[0];
    const float* user_emb = (const float*)d_in[1];
    const float* time_emb = (const float*)d_in[2];
    const float* Wq = (const float*)d_in[3];   const float* bq = (const float*)d_in[4];
    const float* Wk = (const float*)d_in[5];   const float* bk = (const float*)d_in[6];
    const float* Wv = (const float*)d_in[7];   const float* bv = (const float*)d_in[8];
    const float* Wo = (const float*)d_in[9];   const float* bo = (const float*)d_in[10];
    const float* ln1_g = (const float*)d_in[11]; const float* ln1_b = (const float*)d_in[12];
    const float* W1 = (const float*)d_in[13];  const float* b1 = (const float*)d_in[14];
    const float* W2 = (const float*)d_in[15];  const float* b2 = (const float*)d_in[16];
    const float* ln2_g = (const float*)d_in[17]; const float* ln2_b = (const float*)d_in[18];
    const float* fn_g  = (const float*)d_in[19]; const float* fn_b  = (const float*)d_in[20];
    const float* gWl = (const float*)d_in[21]; const float* gWs = (const float*)d_in[22];
    const float* gWt = (const float*)d_in[23]; const float* gbias = (const float*)d_in[24];
    const int* us   = (const int*)d_in[25];
    const int* sess = (const int*)d_in[26];
    const int* tdl  = (const int*)d_in[27];
    const int* pred = (const int*)d_in[28];
    float* out = (float*)d_out;

    float *pS, *pY, *pQ, *pK, *pV, *pT, *pH;
    cudaGetSymbolAddress((void**)&pS, g_S);
    cudaGetSymbolAddress((void**)&pY, g_Yb);
    cudaGetSymbolAddress((void**)&pQ, g_Qb);
    cudaGetSymbolAddress((void**)&pK, g_Kb);
    cudaGetSymbolAddress((void**)&pV, g_Vb);
    cudaGetSymbolAddress((void**)&pT, g_Tb);
    cudaGetSymbolAddress((void**)&pH, g_Hb);

    intra_kernel<<<NTOK, 128>>>(item_emb, sess);
    initS_kernel<<<NTOK*D_MODEL/256, 256>>>();

    const dim3 gP(D_MODEL/64, NTOK/128);   // 256-wide outputs
    const dim3 gF(D_FF/64,   NTOK/128);    // 1024-wide outputs

    for (int blk = 0; blk < N_BLOCKS; blk++) {
        ln_kernel<<<NTOK/8, 256>>>(pS, pY, ln1_g, ln1_b);
        sgemm_kernel<0><<<gP, 256>>>(pY, Wq, bq, nullptr, pQ, NTOK, D_MODEL, D_MODEL);
        sgemm_kernel<0><<<gP, 256>>>(pY, Wk, bk, nullptr, pK, NTOK, D_MODEL, D_MODEL);
        sgemm_kernel<0><<<gP, 256>>>(pY, Wv, bv, nullptr, pV, NTOK, D_MODEL, D_MODEL);
        attn_kernel<<<dim3(BATCH, NHEAD), 128>>>(sess);
        sgemm_kernel<2><<<gP, 256>>>(pT, Wo, bo, pS, pS, NTOK, D_MODEL, D_MODEL);
        ln_kernel<<<NTOK/8, 256>>>(pS, pY, ln2_g, ln2_b);
        sgemm_kernel<1><<<gF, 256>>>(pY, W1, b1, nullptr, pH, NTOK, D_FF, D_MODEL);
        sgemm_kernel<2><<<gP, 256>>>(pH, W2, b2, pS, pS, NTOK, D_MODEL, D_FF);
    }

    ln_kernel<<<NTOK/8, 256>>>(pS, pY, fn_g, fn_b);
    ulong_kernel<<<BATCH, 256>>>(user_emb, us);
    gate_kernel<<<BATCH/8, 256>>>(gWl, gWs, gWt, gbias, time_emb, tdl);
    score_kernel<<<dim3(BATCH, 4), 256>>>(item_emb, pred, out);
}